// round 15
// baseline (speedup 1.0000x reference)
#include <cuda_runtime.h>
#include <cstdint>

#define NN 65536
#define NE 1048576
typedef unsigned long long u64;
typedef long long ll;

// ------------------- device scratch (no allocation allowed) -------------------
__device__ __align__(16) float g_h  [(size_t)NN * 128];
__device__ __align__(16) float g_h2 [(size_t)NN * 128];
__device__ __align__(16) float g_agg[(size_t)NN * 128];
__device__ __align__(16) float g_xw [(size_t)NN * 512];
__device__ float g_dinv[NN];
__device__ float g_bias[512];
__device__ int   g_cnt[NN];
__device__ int   g_cur[NN];
__device__ int   g_indptr[NN + 1];
__device__ __align__(16) int2 g_csr[NE];
__device__ int   g_e32;       // 1 if edge_index is really int32

// ------------------- packed f32x2 helpers -------------------
__device__ __forceinline__ u64 pk2(float x, float y) {
    u64 r; asm("mov.b64 %0,{%1,%2};" : "=l"(r) : "f"(x), "f"(y)); return r;
}
__device__ __forceinline__ u64 pkdup(float x) {
    u64 r; asm("mov.b64 %0,{%1,%1};" : "=l"(r) : "f"(x)); return r;
}
__device__ __forceinline__ void fma2(u64 &d, u64 a, u64 b) {
    asm("fma.rn.f32x2 %0,%1,%2,%0;" : "+l"(d) : "l"(a), "l"(b));
}
__device__ __forceinline__ u64 add2(u64 a, u64 b) {
    u64 r; asm("add.rn.f32x2 %0,%1,%2;" : "=l"(r) : "l"(a), "l"(b)); return r;
}
__device__ __forceinline__ float2 up2(u64 v) {
    float2 r; asm("mov.b64 {%0,%1},%2;" : "=f"(r.x), "=f"(r.y) : "l"(v)); return r;
}

// ------------------- prep: zero + bias + dtype detect -------------------
__global__ __launch_bounds__(1024) void k_prep(const float* __restrict__ bi,
                                               const float* __restrict__ bh,
                                               const ll* __restrict__ ei) {
    int i = blockIdx.x * 1024 + threadIdx.x;
    if (i < NN) g_cnt[i] = 0;
    if (i < 512) g_bias[i] = bi[i] + bh[i];
    if (i == 0) {
        int bad = 0;
        for (int j = 0; j < 64; j++) {
            ll v = ei[j];
            if (v < 0 || v >= NN) bad = 1;
        }
        g_e32 = bad;
    }
}
__global__ __launch_bounds__(256) void k_hist(const ll* __restrict__ ei) {
    int e = blockIdx.x * 256 + threadIdx.x;
    if (e >= NE) return;
    int dst = g_e32 ? ((const int*)ei)[NE + e] : (int)ei[NE + e];
    atomicAdd(&g_cnt[dst], 1);
}
// scan + rsqrt fused (single block)
__global__ __launch_bounds__(1024) void k_scan() {
    __shared__ int ssum[1024];
    int t = threadIdx.x;
    int base = t * 64;
    int s = 0;
    const int4* c4 = (const int4*)&g_cnt[base];
    for (int i = 0; i < 16; i++) {
        int4 v = c4[i];
        s += v.x + v.y + v.z + v.w;
    }
    ssum[t] = s;
    __syncthreads();
    for (int off = 1; off < 1024; off <<= 1) {
        int add = (t >= off) ? ssum[t - off] : 0;
        __syncthreads();
        ssum[t] += add;
        __syncthreads();
    }
    int run = ssum[t] - s;   // exclusive prefix of this chunk
    for (int i = 0; i < 64; i++) {
        int c = g_cnt[base + i];
        g_indptr[base + i] = run;
        g_cur[base + i]    = run;
        g_dinv[base + i]   = rsqrtf(1.0f + (float)c);
        run += c;
    }
    if (t == 1023) g_indptr[NN] = run;
}
__global__ __launch_bounds__(256) void k_scatter(const ll* __restrict__ ei) {
    int e = blockIdx.x * 256 + threadIdx.x;
    if (e >= NE) return;
    int src, dst;
    if (g_e32) {
        const int* p = (const int*)ei;
        src = p[e]; dst = p[NE + e];
    } else {
        src = (int)ei[e]; dst = (int)ei[NE + e];
    }
    int pos = atomicAdd(&g_cur[dst], 1);
    float nm = g_dinv[src] * g_dinv[dst];
    g_csr[pos] = make_int2(src, __float_as_int(nm));
}

// ------------------- tiled GEMM (packed f32x2, 1024 thr, pipelined k-loop) -------------------
// MODE 0: g_h = x @ W1        (fused: g_agg = g_h * dinv^2)
// MODE 1: g_h = g_h2 @ W2     (same fusion)
// MODE 2: g_xw = g_h2 @ W_ih^T + (b_ih + b_hh)
// 1024 threads = 32 warps; warp owns 4 rows x 128 cols; acc = 8 u64/thread.
// k-loop software-pipelined: next k's bv (LDS.128) + 2 A-u64 broadcasts are
// prefetched into registers before the current k's FMA2s consume theirs.
template<int MODE>
__global__ __launch_bounds__(1024, 1)
void k_gemm(const float* __restrict__ Aext, const float* __restrict__ B)
{
    extern __shared__ float sm[];
    float* sB = sm;               // [128][132]  sB[k][n]
    float* sA = sm + 128 * 132;   // [128][132]  sA[k][r]  (A transposed)
    const float* A = (MODE == 0) ? Aext : g_h2;
    const int t = threadIdx.x;
    const int row0 = blockIdx.x * 128;
    const int col0 = (MODE == 2) ? blockIdx.y * 128 : 0;

    // stage A transposed: sA[k][r] = A[row0+r][k]
    for (int idx = t; idx < 128 * 32; idx += 1024) {
        int r = idx >> 5, k4 = idx & 31;
        float4 v = *(const float4*)&A[(size_t)(row0 + r) * 128 + k4 * 4];
        sA[(k4 * 4 + 0) * 132 + r] = v.x;
        sA[(k4 * 4 + 1) * 132 + r] = v.y;
        sA[(k4 * 4 + 2) * 132 + r] = v.z;
        sA[(k4 * 4 + 3) * 132 + r] = v.w;
    }
    if (MODE != 2) {
        for (int idx = t; idx < 128 * 32; idx += 1024) {
            int k = idx >> 5, n4 = idx & 31;
            *(float4*)&sB[k * 132 + n4 * 4] = *(const float4*)&B[(size_t)k * 128 + n4 * 4];
        }
    } else {
        // sB[k][n] = W_ih[col0+n][k]
        for (int idx = t; idx < 128 * 32; idx += 1024) {
            int n = idx >> 5, k4 = idx & 31;
            float4 v = *(const float4*)&B[(size_t)(col0 + n) * 128 + k4 * 4];
            sB[(k4 * 4 + 0) * 132 + n] = v.x;
            sB[(k4 * 4 + 1) * 132 + n] = v.y;
            sB[(k4 * 4 + 2) * 132 + n] = v.z;
            sB[(k4 * 4 + 3) * 132 + n] = v.w;
        }
    }
    __syncthreads();

    const int warp = t >> 5, lane = t & 31;
    const int r0 = warp * 4;     // 32 warps x 4 rows = 128 rows
    const int c0 = lane * 4;     // 32 lanes x 4 cols = 128 cols
    u64 acc[2][4];
#pragma unroll
    for (int i = 0; i < 2; i++)
#pragma unroll
        for (int c = 0; c < 4; c++) acc[i][c] = 0ull;

    const float* bbase = &sB[c0];
    const float* abase = &sA[r0];

    float4 bv = *(const float4*)bbase;
    u64 a0 = *(const u64*)abase;
    u64 a1 = *(const u64*)(abase + 2);

#pragma unroll 4
    for (int k = 0; k < 128; k++) {
        int kn = (k + 1) & 127;            // wraps harmlessly on last iter
        float4 bvn = *(const float4*)(bbase + kn * 132);
        u64 n0 = *(const u64*)(abase + kn * 132);
        u64 n1 = *(const u64*)(abase + kn * 132 + 2);
        u64 b0 = pkdup(bv.x), b1 = pkdup(bv.y), b2 = pkdup(bv.z), b3 = pkdup(bv.w);
        fma2(acc[0][0], a0, b0);
        fma2(acc[0][1], a0, b1);
        fma2(acc[0][2], a0, b2);
        fma2(acc[0][3], a0, b3);
        fma2(acc[1][0], a1, b0);
        fma2(acc[1][1], a1, b1);
        fma2(acc[1][2], a1, b2);
        fma2(acc[1][3], a1, b3);
        bv = bvn; a0 = n0; a1 = n1;
    }

    float4 bb = make_float4(0.f, 0.f, 0.f, 0.f);
    if (MODE == 2) bb = *(const float4*)&g_bias[col0 + c0];
#pragma unroll
    for (int ii = 0; ii < 2; ii++) {
        float2 u0 = up2(acc[ii][0]), u1 = up2(acc[ii][1]);
        float2 u2 = up2(acc[ii][2]), u3 = up2(acc[ii][3]);
        int rA = row0 + r0 + 2 * ii;
        float4 v0 = make_float4(u0.x + bb.x, u1.x + bb.y, u2.x + bb.z, u3.x + bb.w);
        float4 v1 = make_float4(u0.y + bb.x, u1.y + bb.y, u2.y + bb.z, u3.y + bb.w);
        if (MODE == 2) {
            *(float4*)&g_xw[(size_t)rA * 512 + col0 + c0] = v0;
            *(float4*)&g_xw[(size_t)(rA + 1) * 512 + col0 + c0] = v1;
        } else {
            *(float4*)&g_h[(size_t)rA * 128 + c0] = v0;
            *(float4*)&g_h[(size_t)(rA + 1) * 128 + c0] = v1;
            float d0 = g_dinv[rA];     float s0 = d0 * d0;
            float d1 = g_dinv[rA + 1]; float s1 = d1 * d1;
            float4 w0 = make_float4(v0.x * s0, v0.y * s0, v0.z * s0, v0.w * s0);
            float4 w1 = make_float4(v1.x * s1, v1.y * s1, v1.z * s1, v1.w * s1);
            *(float4*)&g_agg[(size_t)rA * 128 + c0] = w0;
            *(float4*)&g_agg[(size_t)(rA + 1) * 128 + c0] = w1;
        }
    }
}

// ------------------- edge aggregation: warp per node -------------------
__global__ __launch_bounds__(256)
void k_agg(const float* __restrict__ bias)
{
    int node = blockIdx.x * 8 + (threadIdx.x >> 5);
    if (node >= NN) return;
    int lane = threadIdx.x & 31;
    int s0 = g_indptr[node], s1 = g_indptr[node + 1];
    float4 acc = *(const float4*)&g_agg[(size_t)node * 128 + lane * 4];

    for (int e = s0; e < s1; e++) {
        int2 cur = __ldg(&g_csr[e]);
        float4 hv = __ldg((const float4*)&g_h[(size_t)cur.x * 128 + lane * 4]);
        float nm = __int_as_float(cur.y);
        acc.x += hv.x * nm; acc.y += hv.y * nm;
        acc.z += hv.z * nm; acc.w += hv.w * nm;
    }
    float4 bb = *(const float4*)&bias[lane * 4];
    float4 o;
    o.x = fmaxf(acc.x + bb.x, 0.f);
    o.y = fmaxf(acc.y + bb.y, 0.f);
    o.z = fmaxf(acc.z + bb.z, 0.f);
    o.w = fmaxf(acc.w + bb.w, 0.f);
    *(float4*)&g_h2[(size_t)node * 128 + lane * 4] = o;
}

// ------------------- LSTM: one CTA per batch (R10 body — best known) -------------------
__device__ __forceinline__ float sigmf_(float x) {
    return __fdividef(1.0f, 1.0f + __expf(-x));
}
__device__ __forceinline__ float tanhf_(float x) {
    float e = __expf(-2.0f * fabsf(x));            // in (0,1], no overflow
    return copysignf(__fdividef(1.0f - e, 1.0f + e), x);
}

__global__ __launch_bounds__(256, 1)
void k_lstm(const float* __restrict__ Whh, float* __restrict__ out)
{
    extern __shared__ float sml[];
    ulonglong2* sw2 = (ulonglong2*)sml;     // [256][16] ulonglong2 = 64 KB
    float* hb = sml + 16384;                // [2][128] double-buffered h

    const int t = threadIdx.x;
    const int b = blockIdx.x;
    const int j = t >> 1;
    const int odd = t & 1;
    const int rowA = odd * 256 + j;
    const int rowB = rowA + 128;
    const int sw_bias = t + 2 * (t >> 3);   // swizzle base (mod 16 applied per q)

    // load weights (packed)
    u64 wA2[64], wB2[32];
    {
        const float2* rA = (const float2*)(Whh + (size_t)rowA * 128);
        const float2* rB = (const float2*)(Whh + (size_t)rowB * 128);
#pragma unroll
        for (int m = 0; m < 64; m++) { float2 v = __ldg(&rA[m]); wA2[m] = pk2(v.x, v.y); }
#pragma unroll
        for (int m = 0; m < 32; m++) { float2 v = __ldg(&rB[m]); wB2[m] = pk2(v.x, v.y); }
        const float4* rB4 = (const float4*)rB;
#pragma unroll
        for (int q = 0; q < 16; q++) {
            float4 v = __ldg(&rB4[16 + q]);
            ulonglong2 w;
            w.x = pk2(v.x, v.y);
            w.y = pk2(v.z, v.w);
            sw2[t * 16 + ((q + sw_bias) & 15)] = w;
        }
    }
    if (t < 128) { hb[t] = 0.f; hb[128 + t] = 0.f; }
    float creg = 0.f;

    const float* xwp = g_xw + ((size_t)b * 1024) * 512;
    float x0 = __ldg(xwp + rowA);
    float x1 = __ldg(xwp + rowB);
    __syncthreads();

    for (int s = 0; s < 1024; s++) {
        float xv0 = x0, xv1 = x1;
        {   // prefetch next step's x projection
            const float* nx = xwp + (size_t)((s < 1023) ? (s + 1) : s) * 512;
            x0 = __ldg(nx + rowA);
            x1 = __ldg(nx + rowB);
        }
        const int p = s & 1;
        const u64* h2 = (const u64*)(hb + p * 128);
        u64 A0 = 0ull, A1 = 0ull, B0 = 0ull, B1 = 0ull, B2 = 0ull;
#pragma unroll
        for (int m = 0; m < 32; m++) {
            u64 hv = h2[m];
            fma2(A0, wA2[m], hv);
            fma2(B0, wB2[m], hv);
        }
#pragma unroll
        for (int m = 32; m < 64; m++) {
            u64 hv = h2[m];
            fma2(A1, wA2[m], hv);
        }
#pragma unroll
        for (int q = 0; q < 16; q++) {
            ulonglong2 w = sw2[t * 16 + ((q + sw_bias) & 15)];
            fma2(B1, w.x, h2[32 + 2 * q]);
            fma2(B2, w.y, h2[33 + 2 * q]);
        }
        float2 pa = up2(add2(A0, A1));
        float2 pb = up2(add2(add2(B0, B1), B2));
        float aA = pa.x + pa.y + xv0;    // even: gate i   | odd: gate g
        float aB = pb.x + pb.y + xv1;    // even: gate f   | odd: gate o
        float nA = __shfl_xor_sync(0xffffffffu, aA, 1);
        float nB = __shfl_xor_sync(0xffffffffu, aB, 1);
        if (!odd) {
            float iv = sigmf_(aA);
            float fv = sigmf_(aB);
            float gv = tanhf_(nA);
            float ov = sigmf_(nB);
            float c = fv * creg + iv * gv;
            creg = c;
            float h = ov * tanhf_(c);
            hb[(p ^ 1) * 128 + j] = h;
            if (s == 1023) out[b * 128 + j] = h;
        }
        __syncthreads();
    }
}

// ------------------- launch -------------------
extern "C" void kernel_launch(void* const* d_in, const int* in_sizes, int n_in,
                              void* d_out, int out_size)
{
    int bi = (n_in >= 11) ? 1 : 0;   // batch_size scalar present or not
    const float* x   = (const float*)d_in[0];
    const ll*    ei  = (const ll*)   d_in[1];
    const float* W1  = (const float*)d_in[2 + bi];
    const float* b1  = (const float*)d_in[3 + bi];
    const float* W2  = (const float*)d_in[4 + bi];
    const float* b2  = (const float*)d_in[5 + bi];
    const float* Wih = (const float*)d_in[6 + bi];
    const float* Whh = (const float*)d_in[7 + bi];
    const float* bih = (const float*)d_in[8 + bi];
    const float* bhh = (const float*)d_in[9 + bi];
    float* out = (float*)d_out;

    const int smemG = 128 * 132 * 4 * 2;        // 135168 B (1 CTA/SM, 32 warps)
    const int smemL = 65536 + 2 * 128 * 4;      // 66560 B
    cudaFuncSetAttribute(k_gemm<0>, cudaFuncAttributeMaxDynamicSharedMemorySize, smemG);
    cudaFuncSetAttribute(k_gemm<1>, cudaFuncAttributeMaxDynamicSharedMemorySize, smemG);
    cudaFuncSetAttribute(k_gemm<2>, cudaFuncAttributeMaxDynamicSharedMemorySize, smemG);
    cudaFuncSetAttribute(k_lstm,    cudaFuncAttributeMaxDynamicSharedMemorySize, smemL);

    k_prep    <<<64, 1024>>>(bih, bhh, ei);
    k_hist    <<<NE / 256, 256>>>(ei);
    k_scan    <<<1, 1024>>>();
    k_gemm<0><<<dim3(512, 1), 1024, smemG>>>(x, W1);
    k_scatter <<<NE / 256, 256>>>(ei);
    k_agg     <<<NN / 8, 256>>>(b1);
    k_gemm<1><<<dim3(512, 1), 1024, smemG>>>(nullptr, W2);
    k_agg     <<<NN / 8, 256>>>(b2);
    k_gemm<2><<<dim3(512, 4), 1024, smemG>>>(nullptr, Wih);
    k_lstm    <<<64, 256, smemL>>>(Whh, out);
    (void)in_sizes; (void)out_size;
}

// round 16
// speedup vs baseline: 1.0372x; 1.0372x over previous
#include <cuda_runtime.h>
#include <cstdint>

#define NN 65536
#define NE 1048576
typedef unsigned long long u64;
typedef long long ll;

// ------------------- device scratch (no allocation allowed) -------------------
__device__ __align__(16) float g_h  [(size_t)NN * 128];
__device__ __align__(16) float g_h2 [(size_t)NN * 128];
__device__ __align__(16) float g_agg[(size_t)NN * 128];
__device__ __align__(16) float g_xw [(size_t)NN * 512];
__device__ float g_dinv[NN];
__device__ float g_bias[512];
__device__ int   g_cnt[NN];
__device__ int   g_cur[NN];
__device__ int   g_indptr[NN + 1];
__device__ __align__(16) int2 g_csr[NE];
__device__ int   g_e32;       // 1 if edge_index is really int32

// ------------------- packed f32x2 helpers -------------------
__device__ __forceinline__ u64 pk2(float x, float y) {
    u64 r; asm("mov.b64 %0,{%1,%2};" : "=l"(r) : "f"(x), "f"(y)); return r;
}
__device__ __forceinline__ u64 pkdup(float x) {
    u64 r; asm("mov.b64 %0,{%1,%1};" : "=l"(r) : "f"(x)); return r;
}
__device__ __forceinline__ void fma2(u64 &d, u64 a, u64 b) {
    asm("fma.rn.f32x2 %0,%1,%2,%0;" : "+l"(d) : "l"(a), "l"(b));
}
__device__ __forceinline__ u64 add2(u64 a, u64 b) {
    u64 r; asm("add.rn.f32x2 %0,%1,%2;" : "=l"(r) : "l"(a), "l"(b)); return r;
}
__device__ __forceinline__ float2 up2(u64 v) {
    float2 r; asm("mov.b64 {%0,%1},%2;" : "=f"(r.x), "=f"(r.y) : "l"(v)); return r;
}

// ------------------- prep: zero + bias + dtype detect -------------------
__global__ __launch_bounds__(1024) void k_prep(const float* __restrict__ bi,
                                               const float* __restrict__ bh,
                                               const ll* __restrict__ ei) {
    int i = blockIdx.x * 1024 + threadIdx.x;
    if (i < NN) g_cnt[i] = 0;
    if (i < 512) g_bias[i] = bi[i] + bh[i];
    if (i == 0) {
        int bad = 0;
        for (int j = 0; j < 64; j++) {
            ll v = ei[j];
            if (v < 0 || v >= NN) bad = 1;
        }
        g_e32 = bad;
    }
}
__global__ __launch_bounds__(256) void k_hist(const ll* __restrict__ ei) {
    int e = blockIdx.x * 256 + threadIdx.x;
    if (e >= NE) return;
    int dst = g_e32 ? ((const int*)ei)[NE + e] : (int)ei[NE + e];
    atomicAdd(&g_cnt[dst], 1);
}
// scan + rsqrt fused (single block)
__global__ __launch_bounds__(1024) void k_scan() {
    __shared__ int ssum[1024];
    int t = threadIdx.x;
    int base = t * 64;
    int s = 0;
    const int4* c4 = (const int4*)&g_cnt[base];
    for (int i = 0; i < 16; i++) {
        int4 v = c4[i];
        s += v.x + v.y + v.z + v.w;
    }
    ssum[t] = s;
    __syncthreads();
    for (int off = 1; off < 1024; off <<= 1) {
        int add = (t >= off) ? ssum[t - off] : 0;
        __syncthreads();
        ssum[t] += add;
        __syncthreads();
    }
    int run = ssum[t] - s;   // exclusive prefix of this chunk
    for (int i = 0; i < 64; i++) {
        int c = g_cnt[base + i];
        g_indptr[base + i] = run;
        g_cur[base + i]    = run;
        g_dinv[base + i]   = rsqrtf(1.0f + (float)c);
        run += c;
    }
    if (t == 1023) g_indptr[NN] = run;
}
__global__ __launch_bounds__(256) void k_scatter(const ll* __restrict__ ei) {
    int e = blockIdx.x * 256 + threadIdx.x;
    if (e >= NE) return;
    int src, dst;
    if (g_e32) {
        const int* p = (const int*)ei;
        src = p[e]; dst = p[NE + e];
    } else {
        src = (int)ei[e]; dst = (int)ei[NE + e];
    }
    int pos = atomicAdd(&g_cur[dst], 1);
    float nm = g_dinv[src] * g_dinv[dst];
    g_csr[pos] = make_int2(src, __float_as_int(nm));
}

// ------------------- tiled GEMM: 8x8 thread tile, 256 thr, 2 CTA/SM -------------------
// MODE 0: g_h = x @ W1        (fused: g_agg = g_h * dinv^2)
// MODE 1: g_h = g_h2 @ W2     (same fusion)
// MODE 2: g_xw = g_h2 @ W_ih^T + (b_ih + b_hh)
// Warp covers 16 rows x 128 cols; lane (rg=l>>4, cg=l&15) owns 8 rows x 8 cols.
// Per k per thread: 2 LDS.128 for A rows (broadcast), 2 LDS.128 for B cols ->
// ~10 wavefronts/warp/k for 32 FMA2 -> FMA-bound (crossbar 10.2K < FMA 16.4K cyc/tile).
// smem = sB[128][132] + sA[64][132] (half-k staged) = 101.4 KB -> 2 CTAs/SM.
#define SB_ELEMS (128 * 132)
#define SA_ELEMS (64 * 132)
template<int MODE>
__global__ __launch_bounds__(256, 2)
void k_gemm(const float* __restrict__ Aext, const float* __restrict__ B)
{
    extern __shared__ float sm[];
    float* sB = sm;               // [128][132]  sB[k][n]
    float* sA = sm + SB_ELEMS;    // [64][132]   sA[kk][r] (half-k, A transposed)
    const float* A = (MODE == 0) ? Aext : g_h2;
    const int t = threadIdx.x;
    const int row0 = blockIdx.x * 128;
    const int col0 = (MODE == 2) ? blockIdx.y * 128 : 0;

    // stage B tile (full k)
    if (MODE != 2) {
        for (int idx = t; idx < 128 * 32; idx += 256) {
            int k = idx >> 5, n4 = idx & 31;
            *(float4*)&sB[k * 132 + n4 * 4] = *(const float4*)&B[(size_t)k * 128 + n4 * 4];
        }
    } else {
        for (int idx = t; idx < 128 * 32; idx += 256) {
            int n = idx >> 5, k4 = idx & 31;
            float4 v = *(const float4*)&B[(size_t)(col0 + n) * 128 + k4 * 4];
            sB[(k4 * 4 + 0) * 132 + n] = v.x;
            sB[(k4 * 4 + 1) * 132 + n] = v.y;
            sB[(k4 * 4 + 2) * 132 + n] = v.z;
            sB[(k4 * 4 + 3) * 132 + n] = v.w;
        }
    }

    const int warp = t >> 5, lane = t & 31;
    const int rg = lane >> 4, cg = lane & 15;
    const int r0 = warp * 16 + rg * 8;   // 8 rows (4 row-pairs)
    const int c0 = cg * 8;               // 8 cols
    u64 acc[4][8];
#pragma unroll
    for (int i = 0; i < 4; i++)
#pragma unroll
        for (int c = 0; c < 8; c++) acc[i][c] = 0ull;

#pragma unroll 1
    for (int half = 0; half < 2; half++) {
        // stage A half-tile transposed: sA[kk][r] = A[row0+r][half*64+kk]
        for (int idx = t; idx < 128 * 16; idx += 256) {
            int r = idx >> 4, k4 = idx & 15;
            float4 v = *(const float4*)&A[(size_t)(row0 + r) * 128 + half * 64 + k4 * 4];
            sA[(k4 * 4 + 0) * 132 + r] = v.x;
            sA[(k4 * 4 + 1) * 132 + r] = v.y;
            sA[(k4 * 4 + 2) * 132 + r] = v.z;
            sA[(k4 * 4 + 3) * 132 + r] = v.w;
        }
        __syncthreads();   // (also covers sB on first pass)

#pragma unroll 2
        for (int kk = 0; kk < 64; kk++) {
            int k = half * 64 + kk;
            float4 bv0 = *(const float4*)&sB[k * 132 + c0];
            float4 bv1 = *(const float4*)&sB[k * 132 + c0 + 4];
            ulonglong2 a01 = *(const ulonglong2*)&sA[kk * 132 + r0];
            ulonglong2 a23 = *(const ulonglong2*)&sA[kk * 132 + r0 + 4];
            u64 bd[8];
            bd[0] = pkdup(bv0.x); bd[1] = pkdup(bv0.y);
            bd[2] = pkdup(bv0.z); bd[3] = pkdup(bv0.w);
            bd[4] = pkdup(bv1.x); bd[5] = pkdup(bv1.y);
            bd[6] = pkdup(bv1.z); bd[7] = pkdup(bv1.w);
            u64 ar[4] = { a01.x, a01.y, a23.x, a23.y };
#pragma unroll
            for (int i = 0; i < 4; i++)
#pragma unroll
                for (int c = 0; c < 8; c++)
                    fma2(acc[i][c], ar[i], bd[c]);
        }
        __syncthreads();   // before overwriting sA
    }

    float4 bbL = make_float4(0.f, 0.f, 0.f, 0.f);
    float4 bbH = make_float4(0.f, 0.f, 0.f, 0.f);
    if (MODE == 2) {
        bbL = *(const float4*)&g_bias[col0 + c0];
        bbH = *(const float4*)&g_bias[col0 + c0 + 4];
    }
#pragma unroll
    for (int ii = 0; ii < 4; ii++) {
        float2 u0 = up2(acc[ii][0]), u1 = up2(acc[ii][1]);
        float2 u2 = up2(acc[ii][2]), u3 = up2(acc[ii][3]);
        float2 u4 = up2(acc[ii][4]), u5 = up2(acc[ii][5]);
        float2 u6 = up2(acc[ii][6]), u7 = up2(acc[ii][7]);
        int rA = row0 + r0 + 2 * ii;
        float4 v0L = make_float4(u0.x + bbL.x, u1.x + bbL.y, u2.x + bbL.z, u3.x + bbL.w);
        float4 v0H = make_float4(u4.x + bbH.x, u5.x + bbH.y, u6.x + bbH.z, u7.x + bbH.w);
        float4 v1L = make_float4(u0.y + bbL.x, u1.y + bbL.y, u2.y + bbL.z, u3.y + bbL.w);
        float4 v1H = make_float4(u4.y + bbH.x, u5.y + bbH.y, u6.y + bbH.z, u7.y + bbH.w);
        if (MODE == 2) {
            *(float4*)&g_xw[(size_t)rA * 512 + col0 + c0] = v0L;
            *(float4*)&g_xw[(size_t)rA * 512 + col0 + c0 + 4] = v0H;
            *(float4*)&g_xw[(size_t)(rA + 1) * 512 + col0 + c0] = v1L;
            *(float4*)&g_xw[(size_t)(rA + 1) * 512 + col0 + c0 + 4] = v1H;
        } else {
            *(float4*)&g_h[(size_t)rA * 128 + c0] = v0L;
            *(float4*)&g_h[(size_t)rA * 128 + c0 + 4] = v0H;
            *(float4*)&g_h[(size_t)(rA + 1) * 128 + c0] = v1L;
            *(float4*)&g_h[(size_t)(rA + 1) * 128 + c0 + 4] = v1H;
            float d0 = g_dinv[rA];     float s0 = d0 * d0;
            float d1 = g_dinv[rA + 1]; float s1 = d1 * d1;
            float4 w0L = make_float4(v0L.x * s0, v0L.y * s0, v0L.z * s0, v0L.w * s0);
            float4 w0H = make_float4(v0H.x * s0, v0H.y * s0, v0H.z * s0, v0H.w * s0);
            float4 w1L = make_float4(v1L.x * s1, v1L.y * s1, v1L.z * s1, v1L.w * s1);
            float4 w1H = make_float4(v1H.x * s1, v1H.y * s1, v1H.z * s1, v1H.w * s1);
            *(float4*)&g_agg[(size_t)rA * 128 + c0] = w0L;
            *(float4*)&g_agg[(size_t)rA * 128 + c0 + 4] = w0H;
            *(float4*)&g_agg[(size_t)(rA + 1) * 128 + c0] = w1L;
            *(float4*)&g_agg[(size_t)(rA + 1) * 128 + c0 + 4] = w1H;
        }
    }
}

// ------------------- edge aggregation: warp per node -------------------
__global__ __launch_bounds__(256)
void k_agg(const float* __restrict__ bias)
{
    int node = blockIdx.x * 8 + (threadIdx.x >> 5);
    if (node >= NN) return;
    int lane = threadIdx.x & 31;
    int s0 = g_indptr[node], s1 = g_indptr[node + 1];
    float4 acc = *(const float4*)&g_agg[(size_t)node * 128 + lane * 4];

    for (int e = s0; e < s1; e++) {
        int2 cur = __ldg(&g_csr[e]);
        float4 hv = __ldg((const float4*)&g_h[(size_t)cur.x * 128 + lane * 4]);
        float nm = __int_as_float(cur.y);
        acc.x += hv.x * nm; acc.y += hv.y * nm;
        acc.z += hv.z * nm; acc.w += hv.w * nm;
    }
    float4 bb = *(const float4*)&bias[lane * 4];
    float4 o;
    o.x = fmaxf(acc.x + bb.x, 0.f);
    o.y = fmaxf(acc.y + bb.y, 0.f);
    o.z = fmaxf(acc.z + bb.z, 0.f);
    o.w = fmaxf(acc.w + bb.w, 0.f);
    *(float4*)&g_h2[(size_t)node * 128 + lane * 4] = o;
}

// ------------------- LSTM: one CTA per batch (R10 body — best known) -------------------
__device__ __forceinline__ float sigmf_(float x) {
    return __fdividef(1.0f, 1.0f + __expf(-x));
}
__device__ __forceinline__ float tanhf_(float x) {
    float e = __expf(-2.0f * fabsf(x));            // in (0,1], no overflow
    return copysignf(__fdividef(1.0f - e, 1.0f + e), x);
}

__global__ __launch_bounds__(256, 1)
void k_lstm(const float* __restrict__ Whh, float* __restrict__ out)
{
    extern __shared__ float sml[];
    ulonglong2* sw2 = (ulonglong2*)sml;     // [256][16] ulonglong2 = 64 KB
    float* hb = sml + 16384;                // [2][128] double-buffered h

    const int t = threadIdx.x;
    const int b = blockIdx.x;
    const int j = t >> 1;
    const int odd = t & 1;
    const int rowA = odd * 256 + j;
    const int rowB = rowA + 128;
    const int sw_bias = t + 2 * (t >> 3);   // swizzle base (mod 16 applied per q)

    // load weights (packed)
    u64 wA2[64], wB2[32];
    {
        const float2* rA = (const float2*)(Whh + (size_t)rowA * 128);
        const float2* rB = (const float2*)(Whh + (size_t)rowB * 128);
#pragma unroll
        for (int m = 0; m < 64; m++) { float2 v = __ldg(&rA[m]); wA2[m] = pk2(v.x, v.y); }
#pragma unroll
        for (int m = 0; m < 32; m++) { float2 v = __ldg(&rB[m]); wB2[m] = pk2(v.x, v.y); }
        const float4* rB4 = (const float4*)rB;
#pragma unroll
        for (int q = 0; q < 16; q++) {
            float4 v = __ldg(&rB4[16 + q]);
            ulonglong2 w;
            w.x = pk2(v.x, v.y);
            w.y = pk2(v.z, v.w);
            sw2[t * 16 + ((q + sw_bias) & 15)] = w;
        }
    }
    if (t < 128) { hb[t] = 0.f; hb[128 + t] = 0.f; }
    float creg = 0.f;

    const float* xwp = g_xw + ((size_t)b * 1024) * 512;
    float x0 = __ldg(xwp + rowA);
    float x1 = __ldg(xwp + rowB);
    __syncthreads();

    for (int s = 0; s < 1024; s++) {
        float xv0 = x0, xv1 = x1;
        {   // prefetch next step's x projection
            const float* nx = xwp + (size_t)((s < 1023) ? (s + 1) : s) * 512;
            x0 = __ldg(nx + rowA);
            x1 = __ldg(nx + rowB);
        }
        const int p = s & 1;
        const u64* h2 = (const u64*)(hb + p * 128);
        u64 A0 = 0ull, A1 = 0ull, B0 = 0ull, B1 = 0ull, B2 = 0ull;
#pragma unroll
        for (int m = 0; m < 32; m++) {
            u64 hv = h2[m];
            fma2(A0, wA2[m], hv);
            fma2(B0, wB2[m], hv);
        }
#pragma unroll
        for (int m = 32; m < 64; m++) {
            u64 hv = h2[m];
            fma2(A1, wA2[m], hv);
        }
#pragma unroll
        for (int q = 0; q < 16; q++) {
            ulonglong2 w = sw2[t * 16 + ((q + sw_bias) & 15)];
            fma2(B1, w.x, h2[32 + 2 * q]);
            fma2(B2, w.y, h2[33 + 2 * q]);
        }
        float2 pa = up2(add2(A0, A1));
        float2 pb = up2(add2(add2(B0, B1), B2));
        float aA = pa.x + pa.y + xv0;    // even: gate i   | odd: gate g
        float aB = pb.x + pb.y + xv1;    // even: gate f   | odd: gate o
        float nA = __shfl_xor_sync(0xffffffffu, aA, 1);
        float nB = __shfl_xor_sync(0xffffffffu, aB, 1);
        if (!odd) {
            float iv = sigmf_(aA);
            float fv = sigmf_(aB);
            float gv = tanhf_(nA);
            float ov = sigmf_(nB);
            float c = fv * creg + iv * gv;
            creg = c;
            float h = ov * tanhf_(c);
            hb[(p ^ 1) * 128 + j] = h;
            if (s == 1023) out[b * 128 + j] = h;
        }
        __syncthreads();
    }
}

// ------------------- launch -------------------
extern "C" void kernel_launch(void* const* d_in, const int* in_sizes, int n_in,
                              void* d_out, int out_size)
{
    int bi = (n_in >= 11) ? 1 : 0;   // batch_size scalar present or not
    const float* x   = (const float*)d_in[0];
    const ll*    ei  = (const ll*)   d_in[1];
    const float* W1  = (const float*)d_in[2 + bi];
    const float* b1  = (const float*)d_in[3 + bi];
    const float* W2  = (const float*)d_in[4 + bi];
    const float* b2  = (const float*)d_in[5 + bi];
    const float* Wih = (const float*)d_in[6 + bi];
    const float* Whh = (const float*)d_in[7 + bi];
    const float* bih = (const float*)d_in[8 + bi];
    const float* bhh = (const float*)d_in[9 + bi];
    float* out = (float*)d_out;

    const int smemG = (SB_ELEMS + SA_ELEMS) * 4;   // 101376 B -> 2 CTA/SM
    const int smemL = 65536 + 2 * 128 * 4;         // 66560 B
    cudaFuncSetAttribute(k_gemm<0>, cudaFuncAttributeMaxDynamicSharedMemorySize, smemG);
    cudaFuncSetAttribute(k_gemm<1>, cudaFuncAttributeMaxDynamicSharedMemorySize, smemG);
    cudaFuncSetAttribute(k_gemm<2>, cudaFuncAttributeMaxDynamicSharedMemorySize, smemG);
    cudaFuncSetAttribute(k_lstm,    cudaFuncAttributeMaxDynamicSharedMemorySize, smemL);

    k_prep    <<<64, 1024>>>(bih, bhh, ei);
    k_hist    <<<NE / 256, 256>>>(ei);
    k_scan    <<<1, 1024>>>();
    k_gemm<0><<<dim3(512, 1), 256, smemG>>>(x, W1);
    k_scatter <<<NE / 256, 256>>>(ei);
    k_agg     <<<NN / 8, 256>>>(b1);
    k_gemm<1><<<dim3(512, 1), 256, smemG>>>(nullptr, W2);
    k_agg     <<<NN / 8, 256>>>(b2);
    k_gemm<2><<<dim3(512, 4), 256, smemG>>>(nullptr, Wih);
    k_lstm    <<<64, 256, smemL>>>(Whh, out);
    (void)in_sizes; (void)out_size;
}